// round 15
// baseline (speedup 1.0000x reference)
#include <cuda_runtime.h>
#include <cstdint>

#define NTOT  16384
#define NHALF 8192
#define DDIM  64
#define TPB   256
#define STRIDE 68   // padded smem row stride (floats) -> conflict-free fragment LDS

// dynamic smem: sA(128*68f) | sB(128*68f) | sqA(128f) | sqB(128f) | red(8 dbl)
#define SMEM_BYTES (2*128*STRIDE*4 + 256*4 + 8*8)

// ---------------- device scratch ----------------
__device__ float  g_z[NTOT * DDIM];    // row-major z, pre-rounded to tf32
__device__ float  g_sq[NTOT];          // fp32 row squared norms (raw values)
__device__ double g_S;
__device__ double g_col[DDIM];
__device__ double g_acc[3];            // XX, XY, YY partial sums
__device__ float  g_c4;                // -log2(e)/(4*bw)

// ---------------- helpers ----------------
__device__ __forceinline__ float ex2f(float x) {
    float r; asm("ex2.approx.f32 %0, %1;" : "=f"(r) : "f"(x)); return r;
}
__device__ __forceinline__ float to_tf32(float v) {
    uint32_t r; asm("cvt.rna.tf32.f32 %0, %1;" : "=r"(r) : "f"(v));
    return __uint_as_float(r);
}
__device__ __forceinline__ uint64_t pk2(float lo, float hi) {
    uint64_t r; asm("mov.b64 %0, {%1,%2};" : "=l"(r) : "f"(lo), "f"(hi)); return r;
}
__device__ __forceinline__ void upk2(uint64_t v, float& lo, float& hi) {
    asm("mov.b64 {%0,%1}, %2;" : "=f"(lo), "=f"(hi) : "l"(v));
}
__device__ __forceinline__ uint64_t mul2(uint64_t a, uint64_t b) {
    uint64_t d; asm("mul.rn.f32x2 %0, %1, %2;" : "=l"(d) : "l"(a), "l"(b)); return d;
}
__device__ __forceinline__ uint64_t add2(uint64_t a, uint64_t b) {
    uint64_t d; asm("add.rn.f32x2 %0, %1, %2;" : "=l"(d) : "l"(a), "l"(b)); return d;
}
__device__ __forceinline__ uint64_t fma2(uint64_t a, uint64_t b, uint64_t c) {
    uint64_t d; asm("fma.rn.f32x2 %0, %1, %2, %3;" : "=l"(d) : "l"(a), "l"(b), "l"(c)); return d;
}
// K(u) = s + s^2 + s^4 + s^8 + s^16, s = 2^u  (packed 2-wide)
__device__ __forceinline__ uint64_t kchain2(uint64_t u2) {
    float u0, u1; upk2(u2, u0, u1);
    uint64_t s   = pk2(ex2f(u0), ex2f(u1));
    uint64_t s2  = mul2(s, s);
    uint64_t s4  = mul2(s2, s2);
    uint64_t s8  = mul2(s4, s4);
    uint64_t s16 = mul2(s8, s8);
    return add2(add2(s, s2), add2(s4, add2(s8, s16)));
}
__device__ __forceinline__ float kchain1(float u) {
    float s = ex2f(u);
    float s2 = s * s, s4 = s2 * s2, s8 = s4 * s4, s16 = s8 * s8;
    return s + s2 + s4 + s8 + s16;
}
__device__ __forceinline__ void mma8(float c[4],
                                     uint32_t a0, uint32_t a1, uint32_t a2, uint32_t a3,
                                     uint32_t b0, uint32_t b1) {
    asm volatile(
        "mma.sync.aligned.m16n8k8.row.col.f32.tf32.tf32.f32 "
        "{%0,%1,%2,%3}, {%4,%5,%6,%7}, {%8,%9}, {%0,%1,%2,%3};"
        : "+f"(c[0]), "+f"(c[1]), "+f"(c[2]), "+f"(c[3])
        : "r"(a0), "r"(a1), "r"(a2), "r"(a3), "r"(b0), "r"(b1));
}

// ---------------- 1) zero accumulators ----------------
__global__ void k_init() {
    int t = threadIdx.x;
    if (t == 0) g_S = 0.0;
    if (t < DDIM) g_col[t] = 0.0;
    if (t < 3) g_acc[t] = 0.0;
}

// ---------------- 2) prep: tf32 copy, sq norms, bw reductions ----------------
__global__ void k_prep(const float* __restrict__ x, const float* __restrict__ y) {
    int t = threadIdx.x;
    int lane = t & 31, w = t >> 5;
    __shared__ double scol[DDIM];
    __shared__ double sS;
    if (t < DDIM) scol[t] = 0.0;
    if (t == 0) sS = 0.0;
    __syncthreads();

    double c0 = 0.0, c1 = 0.0, lS = 0.0;
    int rowbase = blockIdx.x * 256 + w * 32;
    for (int rr = 0; rr < 32; rr++) {
        int row = rowbase + rr;
        const float* z = (row < NHALF) ? (x + (size_t)row * DDIM)
                                       : (y + (size_t)(row - NHALF) * DDIM);
        float v0 = z[lane];
        float v1 = z[lane + 32];
        g_z[(size_t)row * DDIM + lane]      = to_tf32(v0);
        g_z[(size_t)row * DDIM + lane + 32] = to_tf32(v1);
        float s = v0 * v0 + v1 * v1;
        #pragma unroll
        for (int o = 16; o; o >>= 1) s += __shfl_xor_sync(0xffffffffu, s, o);
        if (lane == 0) { g_sq[row] = s; lS += (double)s; }
        c0 += (double)v0;
        c1 += (double)v1;
    }
    atomicAdd(&scol[lane], c0);
    atomicAdd(&scol[lane + 32], c1);
    if (lane == 0) atomicAdd(&sS, lS);
    __syncthreads();
    if (t < DDIM) atomicAdd(&g_col[t], scol[t]);
    if (t == 0) atomicAdd(&g_S, sS);
}

// ---------------- 3) bandwidth (closed form) ----------------
__global__ void k_bw() {
    int t = threadIdx.x;   // 64 threads
    __shared__ double sh[2];
    double v = g_col[t];
    double v2 = v * v;
    #pragma unroll
    for (int o = 16; o; o >>= 1) v2 += __shfl_xor_sync(0xffffffffu, v2, o);
    if ((t & 31) == 0) sh[t >> 5] = v2;
    __syncthreads();
    if (t == 0) {
        double N = (double)NTOT;
        double sumd2 = 2.0 * N * g_S - 2.0 * (sh[0] + sh[1]);
        double bw = sumd2 / (N * N - N);
        g_c4 = (float)(-1.4426950408889634 / (4.0 * bw));
    }
}

// ---------------- 4) main: tf32 mma.sync gram + fused multi-RBF epilogue ----
__global__ void __launch_bounds__(TPB, 2) k_main() {
    int bi = blockIdx.y, bj = blockIdx.x;
    if (bj < bi) return;                       // upper triangle only
    extern __shared__ char smem[];
    float*  sA  = (float*)smem;                // 128 x STRIDE
    float*  sB  = sA + 128 * STRIDE;
    float*  sqA = sB + 128 * STRIDE;           // 128, pre-scaled by c4
    float*  sqB = sqA + 128;
    double* red = (double*)(sqB + 128);        // 8

    int t = threadIdx.x, w = t >> 5, lane = t & 31;
    int gid = lane >> 2, tig = lane & 3;
    bool diag = (bi == bj);
    int cls = (bi < 64) ? ((bj < 64) ? 0 : 1) : 2;
    int rowbase = bi * 128, colbase = bj * 128;

    float c4 = g_c4;
    if (t < 128) sqA[t]       = g_sq[rowbase + t] * c4;
    else         sqB[t - 128] = g_sq[colbase + (t - 128)] * c4;

    #pragma unroll
    for (int it = 0; it < 8; it++) {
        int lin = t + it * 256;
        int r = lin >> 4, c = (lin & 15) << 2;
        *(float4*)&sA[r * STRIDE + c] = *(const float4*)&g_z[(size_t)(rowbase + r) * DDIM + c];
        *(float4*)&sB[r * STRIDE + c] = *(const float4*)&g_z[(size_t)(colbase + r) * DDIM + c];
    }
    __syncthreads();

    int wm = w >> 2, wn = w & 3;               // warp tile: 64 rows x 32 cols
    const float* Abase = sA + (wm * 64 + gid) * STRIDE + tig;
    const float* Bbase = sB + (wn * 32 + gid) * STRIDE + tig;

    float acc[4][4][4] = {};
    #pragma unroll
    for (int k = 0; k < 8; k++) {
        uint32_t a[4][4], b[4][2];
        #pragma unroll
        for (int mt = 0; mt < 4; mt++) {
            const float* p = Abase + mt * 16 * STRIDE + k * 8;
            a[mt][0] = __float_as_uint(p[0]);
            a[mt][1] = __float_as_uint(p[8 * STRIDE]);
            a[mt][2] = __float_as_uint(p[4]);
            a[mt][3] = __float_as_uint(p[8 * STRIDE + 4]);
        }
        #pragma unroll
        for (int nt = 0; nt < 4; nt++) {
            const float* p = Bbase + nt * 8 * STRIDE + k * 8;
            b[nt][0] = __float_as_uint(p[0]);
            b[nt][1] = __float_as_uint(p[4]);
        }
        #pragma unroll
        for (int mt = 0; mt < 4; mt++)
            #pragma unroll
            for (int nt = 0; nt < 4; nt++)
                mma8(acc[mt][nt], a[mt][0], a[mt][1], a[mt][2], a[mt][3],
                     b[nt][0], b[nt][1]);
    }

    // epilogue: u = (si + sj - 2*dot)*c4 ; K = s+s^2+s^4+s^8+s^16, s=2^u
    float m2s = -2.f * c4;
    uint64_t m2v = pk2(m2s, m2s);
    uint64_t acc2 = pk2(0.f, 0.f);
    float accd = 0.f;

    if (!diag) {
        #pragma unroll
        for (int mt = 0; mt < 4; mt++) {
            float sia = sqA[wm * 64 + mt * 16 + gid];
            float sib = sqA[wm * 64 + mt * 16 + gid + 8];
            uint64_t sia2 = pk2(sia, sia);
            uint64_t sib2 = pk2(sib, sib);
            #pragma unroll
            for (int nt = 0; nt < 4; nt++) {
                uint64_t sj2 = *(const uint64_t*)&sqB[wn * 32 + nt * 8 + 2 * tig];
                uint64_t d0 = pk2(acc[mt][nt][0], acc[mt][nt][1]);
                uint64_t d1 = pk2(acc[mt][nt][2], acc[mt][nt][3]);
                acc2 = add2(acc2, kchain2(fma2(d0, m2v, add2(sia2, sj2))));
                acc2 = add2(acc2, kchain2(fma2(d1, m2v, add2(sib2, sj2))));
            }
        }
    } else {
        #pragma unroll
        for (int mt = 0; mt < 4; mt++) {
            int gia = wm * 64 + mt * 16 + gid;
            int gib = gia + 8;
            float sia = sqA[gia], sib = sqA[gib];
            #pragma unroll
            for (int nt = 0; nt < 4; nt++) {
                int gj0 = wn * 32 + nt * 8 + 2 * tig;
                float sj0 = sqB[gj0], sj1 = sqB[gj0 + 1];
                float u;
                u = fmaf(acc[mt][nt][0], m2s, sia + sj0);
                if (gj0     > gia) accd += 2.f * kchain1(u);
                u = fmaf(acc[mt][nt][1], m2s, sia + sj1);
                if (gj0 + 1 > gia) accd += 2.f * kchain1(u);
                u = fmaf(acc[mt][nt][2], m2s, sib + sj0);
                if (gj0     > gib) accd += 2.f * kchain1(u);
                u = fmaf(acc[mt][nt][3], m2s, sib + sj1);
                if (gj0 + 1 > gib) accd += 2.f * kchain1(u);
            }
        }
    }

    double dp;
    if (diag) dp = (double)accd;
    else {
        float a0, a1; upk2(acc2, a0, a1);
        double wB = (cls == 1) ? 1.0 : 2.0;
        dp = wB * ((double)a0 + (double)a1);
    }
    #pragma unroll
    for (int o = 16; o; o >>= 1) dp += __shfl_xor_sync(0xffffffffu, dp, o);
    if (lane == 0) red[w] = dp;
    __syncthreads();
    if (t == 0) {
        double s = 0.0;
        #pragma unroll
        for (int i = 0; i < 8; i++) s += red[i];
        atomicAdd(&g_acc[cls], s);
    }
}

// ---------------- 5) finalize ----------------
__global__ void k_fin(float* out) {
    double diagsum = 5.0 * (double)NHALF;      // K(0) = 5 per diagonal element
    double XX = g_acc[0] + diagsum;
    double YY = g_acc[2] + diagsum;
    double XY = g_acc[1];
    double n2 = (double)NHALF * (double)NHALF;
    out[0] = (float)((XX - 2.0 * XY + YY) / n2);
}

// ---------------- launch ----------------
extern "C" void kernel_launch(void* const* d_in, const int* in_sizes, int n_in,
                              void* d_out, int out_size) {
    const float* x = (const float*)d_in[0];
    const float* y = (const float*)d_in[1];
    cudaFuncSetAttribute(k_main, cudaFuncAttributeMaxDynamicSharedMemorySize, SMEM_BYTES);
    k_init<<<1, 64>>>();
    k_prep<<<64, 256>>>(x, y);
    k_bw<<<1, 64>>>();
    dim3 grid(128, 128);
    k_main<<<grid, TPB, SMEM_BYTES>>>();
    k_fin<<<1, 1>>>((float*)d_out);
}

// round 16
// speedup vs baseline: 1.0077x; 1.0077x over previous
#include <cuda_runtime.h>
#include <cstdint>

#define NTOT  16384
#define NHALF 8192
#define DDIM  64
#define TPB   256
#define STRIDE 68   // padded smem row stride (floats) -> conflict-free fragment LDS

// dynamic smem: sA(128*68f) | sB(128*68f) | sqA(128f) | sqB(128f) | red(8 dbl)
#define SMEM_BYTES (2*128*STRIDE*4 + 256*4 + 8*8)

// ---------------- device scratch ----------------
__device__ float  g_z[NTOT * DDIM];    // row-major z, pre-rounded to tf32
__device__ float  g_sq[NTOT];          // fp32 row squared norms (raw values)
__device__ double g_S;
__device__ double g_col[DDIM];
__device__ double g_acc[3];            // XX, XY, YY partial sums
__device__ float  g_c4;                // -log2(e)/(4*bw)

// ---------------- helpers ----------------
__device__ __forceinline__ float ex2f(float x) {
    float r; asm("ex2.approx.f32 %0, %1;" : "=f"(r) : "f"(x)); return r;
}
__device__ __forceinline__ float to_tf32(float v) {
    uint32_t r; asm("cvt.rna.tf32.f32 %0, %1;" : "=r"(r) : "f"(v));
    return __uint_as_float(r);
}
__device__ __forceinline__ uint64_t pk2(float lo, float hi) {
    uint64_t r; asm("mov.b64 %0, {%1,%2};" : "=l"(r) : "f"(lo), "f"(hi)); return r;
}
__device__ __forceinline__ void upk2(uint64_t v, float& lo, float& hi) {
    asm("mov.b64 {%0,%1}, %2;" : "=f"(lo), "=f"(hi) : "l"(v));
}
__device__ __forceinline__ uint64_t mul2(uint64_t a, uint64_t b) {
    uint64_t d; asm("mul.rn.f32x2 %0, %1, %2;" : "=l"(d) : "l"(a), "l"(b)); return d;
}
__device__ __forceinline__ uint64_t add2(uint64_t a, uint64_t b) {
    uint64_t d; asm("add.rn.f32x2 %0, %1, %2;" : "=l"(d) : "l"(a), "l"(b)); return d;
}
__device__ __forceinline__ uint64_t fma2(uint64_t a, uint64_t b, uint64_t c) {
    uint64_t d; asm("fma.rn.f32x2 %0, %1, %2, %3;" : "=l"(d) : "l"(a), "l"(b), "l"(c)); return d;
}
// K(u) = s + s^2 + s^4 + s^8 + s^16, s = 2^u  (packed 2-wide)
__device__ __forceinline__ uint64_t kchain2(uint64_t u2) {
    float u0, u1; upk2(u2, u0, u1);
    uint64_t s   = pk2(ex2f(u0), ex2f(u1));
    uint64_t s2  = mul2(s, s);
    uint64_t s4  = mul2(s2, s2);
    uint64_t s8  = mul2(s4, s4);
    uint64_t s16 = mul2(s8, s8);
    return add2(add2(s, s2), add2(s4, add2(s8, s16)));
}
__device__ __forceinline__ float kchain1(float u) {
    float s = ex2f(u);
    float s2 = s * s, s4 = s2 * s2, s8 = s4 * s4, s16 = s8 * s8;
    return s + s2 + s4 + s8 + s16;
}
__device__ __forceinline__ void mma8(float c[4],
                                     uint32_t a0, uint32_t a1, uint32_t a2, uint32_t a3,
                                     uint32_t b0, uint32_t b1) {
    asm volatile(
        "mma.sync.aligned.m16n8k8.row.col.f32.tf32.tf32.f32 "
        "{%0,%1,%2,%3}, {%4,%5,%6,%7}, {%8,%9}, {%0,%1,%2,%3};"
        : "+f"(c[0]), "+f"(c[1]), "+f"(c[2]), "+f"(c[3])
        : "r"(a0), "r"(a1), "r"(a2), "r"(a3), "r"(b0), "r"(b1));
}

// ---------------- 1) zero accumulators ----------------
__global__ void k_init() {
    int t = threadIdx.x;
    if (t == 0) g_S = 0.0;
    if (t < DDIM) g_col[t] = 0.0;
    if (t < 3) g_acc[t] = 0.0;
}

// ---------------- 2) prep: tf32 copy, sq norms, bw reductions ----------------
__global__ void k_prep(const float* __restrict__ x, const float* __restrict__ y) {
    int t = threadIdx.x;
    int lane = t & 31, w = t >> 5;
    __shared__ double scol[DDIM];
    __shared__ double sS;
    if (t < DDIM) scol[t] = 0.0;
    if (t == 0) sS = 0.0;
    __syncthreads();

    double c0 = 0.0, c1 = 0.0, lS = 0.0;
    int rowbase = blockIdx.x * 256 + w * 32;
    for (int rr = 0; rr < 32; rr++) {
        int row = rowbase + rr;
        const float* z = (row < NHALF) ? (x + (size_t)row * DDIM)
                                       : (y + (size_t)(row - NHALF) * DDIM);
        float v0 = z[lane];
        float v1 = z[lane + 32];
        g_z[(size_t)row * DDIM + lane]      = to_tf32(v0);
        g_z[(size_t)row * DDIM + lane + 32] = to_tf32(v1);
        float s = v0 * v0 + v1 * v1;
        #pragma unroll
        for (int o = 16; o; o >>= 1) s += __shfl_xor_sync(0xffffffffu, s, o);
        if (lane == 0) { g_sq[row] = s; lS += (double)s; }
        c0 += (double)v0;
        c1 += (double)v1;
    }
    atomicAdd(&scol[lane], c0);
    atomicAdd(&scol[lane + 32], c1);
    if (lane == 0) atomicAdd(&sS, lS);
    __syncthreads();
    if (t < DDIM) atomicAdd(&g_col[t], scol[t]);
    if (t == 0) atomicAdd(&g_S, sS);
}

// ---------------- 3) bandwidth (closed form) ----------------
__global__ void k_bw() {
    int t = threadIdx.x;   // 64 threads
    __shared__ double sh[2];
    double v = g_col[t];
    double v2 = v * v;
    #pragma unroll
    for (int o = 16; o; o >>= 1) v2 += __shfl_xor_sync(0xffffffffu, v2, o);
    if ((t & 31) == 0) sh[t >> 5] = v2;
    __syncthreads();
    if (t == 0) {
        double N = (double)NTOT;
        double sumd2 = 2.0 * N * g_S - 2.0 * (sh[0] + sh[1]);
        double bw = sumd2 / (N * N - N);
        g_c4 = (float)(-1.4426950408889634 / (4.0 * bw));
    }
}

// ---------------- 4) main: tf32 mma.sync gram + fused multi-RBF epilogue ----
__global__ void __launch_bounds__(TPB, 2) k_main() {
    int bi = blockIdx.y, bj = blockIdx.x;
    if (bj < bi) return;                       // upper triangle only
    extern __shared__ char smem[];
    float*  sA  = (float*)smem;                // 128 x STRIDE
    float*  sB  = sA + 128 * STRIDE;
    float*  sqA = sB + 128 * STRIDE;           // 128, pre-scaled by c4
    float*  sqB = sqA + 128;
    double* red = (double*)(sqB + 128);        // 8

    int t = threadIdx.x, w = t >> 5, lane = t & 31;
    int gid = lane >> 2, tig = lane & 3;
    bool diag = (bi == bj);
    int cls = (bi < 64) ? ((bj < 64) ? 0 : 1) : 2;
    int rowbase = bi * 128, colbase = bj * 128;

    float c4 = g_c4;
    if (t < 128) sqA[t]       = g_sq[rowbase + t] * c4;
    else         sqB[t - 128] = g_sq[colbase + (t - 128)] * c4;

    #pragma unroll
    for (int it = 0; it < 8; it++) {
        int lin = t + it * 256;
        int r = lin >> 4, c = (lin & 15) << 2;
        *(float4*)&sA[r * STRIDE + c] = *(const float4*)&g_z[(size_t)(rowbase + r) * DDIM + c];
        *(float4*)&sB[r * STRIDE + c] = *(const float4*)&g_z[(size_t)(colbase + r) * DDIM + c];
    }
    __syncthreads();

    int wm = w >> 2, wn = w & 3;               // warp tile: 64 rows x 32 cols
    const float* Abase = sA + (wm * 64 + gid) * STRIDE + tig;
    const float* Bbase = sB + (wn * 32 + gid) * STRIDE + tig;

    float acc[4][4][4] = {};
    #pragma unroll
    for (int k = 0; k < 8; k++) {
        uint32_t a[4][4], b[4][2];
        #pragma unroll
        for (int mt = 0; mt < 4; mt++) {
            const float* p = Abase + mt * 16 * STRIDE + k * 8;
            a[mt][0] = __float_as_uint(p[0]);
            a[mt][1] = __float_as_uint(p[8 * STRIDE]);
            a[mt][2] = __float_as_uint(p[4]);
            a[mt][3] = __float_as_uint(p[8 * STRIDE + 4]);
        }
        #pragma unroll
        for (int nt = 0; nt < 4; nt++) {
            const float* p = Bbase + nt * 8 * STRIDE + k * 8;
            b[nt][0] = __float_as_uint(p[0]);
            b[nt][1] = __float_as_uint(p[4]);
        }
        #pragma unroll
        for (int mt = 0; mt < 4; mt++)
            #pragma unroll
            for (int nt = 0; nt < 4; nt++)
                mma8(acc[mt][nt], a[mt][0], a[mt][1], a[mt][2], a[mt][3],
                     b[nt][0], b[nt][1]);
    }

    // epilogue: u = (si + sj - 2*dot)*c4 ; K = s+s^2+s^4+s^8+s^16, s=2^u
    float m2s = -2.f * c4;
    uint64_t m2v = pk2(m2s, m2s);
    uint64_t acc2 = pk2(0.f, 0.f);
    float accd = 0.f;

    if (!diag) {
        #pragma unroll
        for (int mt = 0; mt < 4; mt++) {
            float sia = sqA[wm * 64 + mt * 16 + gid];
            float sib = sqA[wm * 64 + mt * 16 + gid + 8];
            uint64_t sia2 = pk2(sia, sia);
            uint64_t sib2 = pk2(sib, sib);
            #pragma unroll
            for (int nt = 0; nt < 4; nt++) {
                uint64_t sj2 = *(const uint64_t*)&sqB[wn * 32 + nt * 8 + 2 * tig];
                uint64_t d0 = pk2(acc[mt][nt][0], acc[mt][nt][1]);
                uint64_t d1 = pk2(acc[mt][nt][2], acc[mt][nt][3]);
                acc2 = add2(acc2, kchain2(fma2(d0, m2v, add2(sia2, sj2))));
                acc2 = add2(acc2, kchain2(fma2(d1, m2v, add2(sib2, sj2))));
            }
        }
    } else {
        #pragma unroll
        for (int mt = 0; mt < 4; mt++) {
            int gia = wm * 64 + mt * 16 + gid;
            int gib = gia + 8;
            float sia = sqA[gia], sib = sqA[gib];
            #pragma unroll
            for (int nt = 0; nt < 4; nt++) {
                int gj0 = wn * 32 + nt * 8 + 2 * tig;
                float sj0 = sqB[gj0], sj1 = sqB[gj0 + 1];
                float u;
                u = fmaf(acc[mt][nt][0], m2s, sia + sj0);
                if (gj0     > gia) accd += 2.f * kchain1(u);
                u = fmaf(acc[mt][nt][1], m2s, sia + sj1);
                if (gj0 + 1 > gia) accd += 2.f * kchain1(u);
                u = fmaf(acc[mt][nt][2], m2s, sib + sj0);
                if (gj0     > gib) accd += 2.f * kchain1(u);
                u = fmaf(acc[mt][nt][3], m2s, sib + sj1);
                if (gj0 + 1 > gib) accd += 2.f * kchain1(u);
            }
        }
    }

    double dp;
    if (diag) dp = (double)accd;
    else {
        float a0, a1; upk2(acc2, a0, a1);
        double wB = (cls == 1) ? 1.0 : 2.0;
        dp = wB * ((double)a0 + (double)a1);
    }
    #pragma unroll
    for (int o = 16; o; o >>= 1) dp += __shfl_xor_sync(0xffffffffu, dp, o);
    if (lane == 0) red[w] = dp;
    __syncthreads();
    if (t == 0) {
        double s = 0.0;
        #pragma unroll
        for (int i = 0; i < 8; i++) s += red[i];
        atomicAdd(&g_acc[cls], s);
    }
}

// ---------------- 5) finalize ----------------
__global__ void k_fin(float* out) {
    double diagsum = 5.0 * (double)NHALF;      // K(0) = 5 per diagonal element
    double XX = g_acc[0] + diagsum;
    double YY = g_acc[2] + diagsum;
    double XY = g_acc[1];
    double n2 = (double)NHALF * (double)NHALF;
    out[0] = (float)((XX - 2.0 * XY + YY) / n2);
}

// ---------------- launch ----------------
extern "C" void kernel_launch(void* const* d_in, const int* in_sizes, int n_in,
                              void* d_out, int out_size) {
    const float* x = (const float*)d_in[0];
    const float* y = (const float*)d_in[1];
    cudaFuncSetAttribute(k_main, cudaFuncAttributeMaxDynamicSharedMemorySize, SMEM_BYTES);
    k_init<<<1, 64>>>();
    k_prep<<<64, 256>>>(x, y);
    k_bw<<<1, 64>>>();
    dim3 grid(128, 128);
    k_main<<<grid, TPB, SMEM_BYTES>>>();
    k_fin<<<1, 1>>>((float*)d_out);
}